// round 16
// baseline (speedup 1.0000x reference)
#include <cuda_runtime.h>
#include <cuda_fp16.h>
#include <mma.h>

using namespace nvcuda;

#define NN 4096
#define DD 512
#define EE 65536

// ---------------- static device scratch (allocation-free rule) ----------------
__device__ __half g_Hah[(size_t)NN * NN];     // P ping
__device__ __half g_Hbh[(size_t)NN * NN];     // P pong (final P lands here)
__device__ __half g_Y0[(size_t)NN * 1024];    // [X | Xw] fp16
__device__ __half g_Ya[(size_t)NN * 1024];    // thin ping / final -2*pX
__device__ __half g_Yb[(size_t)NN * 1024];    // thin pong (final [pX | pXw])
__device__ float g_a[NN];                     // P*u
__device__ float g_b[NN];                     // P*1
__device__ int   g_rowptr[NN + 1];
__device__ int   g_cur[NN];
__device__ int   g_cols[EE + NN];
__device__ float g_vals[EE + NN];
__device__ float g_dis[NN];
__device__ float g_sq[NN];
__device__ int   g_degdst[NN];
__device__ int   g_degrow[NN];

// ---------------- streams/events for fork-join overlap (created at load time,
// host-side only; no device allocation inside kernel_launch) ----------------
struct HxStreams {
    cudaStream_t side;
    cudaEvent_t eRoot, eCsr, eSq, eSide;
    HxStreams() {
        cudaStreamCreateWithFlags(&side, cudaStreamNonBlocking);
        cudaEventCreateWithFlags(&eRoot, cudaEventDisableTiming);
        cudaEventCreateWithFlags(&eCsr, cudaEventDisableTiming);
        cudaEventCreateWithFlags(&eSq, cudaEventDisableTiming);
        cudaEventCreateWithFlags(&eSide, cudaEventDisableTiming);
    }
};
static HxStreams hx;

// ---------------- graph preprocessing ----------------
__global__ void init_kernel() {
    int i = blockIdx.x * blockDim.x + threadIdx.x;
    if (i < NN) { g_degdst[i] = 1; g_degrow[i] = 0; }
}

__global__ void count_kernel(const int* __restrict__ src, const int* __restrict__ dst) {
    int i = blockIdx.x * blockDim.x + threadIdx.x;
    if (i < EE) {
        atomicAdd(&g_degdst[dst[i]], 1);
        atomicAdd(&g_degrow[src[i]], 1);
    }
}

// single block, 1024 threads, 4 elements each: exclusive scan of g_degdst -> rowptr
__global__ void scan_kernel() {
    __shared__ int part[1024];
    int t = threadIdx.x;
    int v[4];
    int s = 0;
#pragma unroll
    for (int j = 0; j < 4; j++) { v[j] = g_degdst[t * 4 + j]; s += v[j]; }
    part[t] = s;
    __syncthreads();
    for (int off = 1; off < 1024; off <<= 1) {
        int x = 0;
        if (t >= off) x = part[t - off];
        __syncthreads();
        if (t >= off) part[t] += x;
        __syncthreads();
    }
    int base = part[t] - s;
    int run = base;
#pragma unroll
    for (int j = 0; j < 4; j++) {
        int idx = t * 4 + j;
        g_rowptr[idx] = run;
        g_cur[idx] = run;
        g_dis[idx] = rsqrtf((float)v[j]);
        run += v[j];
    }
    if (t == 1023) g_rowptr[NN] = part[1023];
}

__global__ void fill_kernel(const int* __restrict__ src, const int* __restrict__ dst) {
    int i = blockIdx.x * blockDim.x + threadIdx.x;
    if (i < EE) {
        int s = src[i], d = dst[i];
        int p = atomicAdd(&g_cur[d], 1);
        g_cols[p] = s;
        g_vals[p] = g_dis[s] * g_dis[d];
    } else if (i < EE + NN) {
        int n = i - EE;
        int p = atomicAdd(&g_cur[n], 1);
        g_cols[p] = n;
        g_vals[p] = g_dis[n] * g_dis[n];
    }
}

// ---------------- sq + Y0 build (side stream; inputs only) ----------------
__global__ void sq_kernel(const float* __restrict__ x, const float* __restrict__ w) {
    __shared__ float red[4];
    int r = blockIdx.x;
    int t = threadIdx.x;
    float s = 0.f;
    for (int d = t; d < DD; d += 128) {
        float xv = x[r * DD + d];
        float wv = w[d];
        s += wv * xv * xv;
        g_Y0[(size_t)r * 1024 + d] = __float2half_rn(xv);
        g_Y0[(size_t)r * 1024 + 512 + d] = __float2half_rn(xv * wv);
    }
#pragma unroll
    for (int o = 16; o > 0; o >>= 1) s += __shfl_xor_sync(0xffffffffu, s, o);
    if ((t & 31) == 0) red[t >> 5] = s;
    __syncthreads();
    if (t == 0) g_sq[r] = red[0] + red[1] + red[2] + red[3];
}

// ---------------- P1 = 0.5*Ahat + 0.5*I ----------------
__global__ void p1_init_kernel() {
    int r = blockIdx.x;
    int c = (blockIdx.y << 11) + (threadIdx.x << 3);
    uint4 z = make_uint4(0u, 0u, 0u, 0u);
    *(uint4*)(g_Hah + (size_t)r * NN + c) = z;
    if (r >= c && r < c + 8) g_Hah[(size_t)r * NN + r] = __float2half_rn(0.5f);
}

__global__ void p1_scatter_kernel(const int* __restrict__ src, const int* __restrict__ dst) {
    int i = blockIdx.x * blockDim.x + threadIdx.x;
    if (i < EE) {
        int s = src[i], d = dst[i];
        atomicAdd(&g_Hah[(size_t)d * NN + s], __float2half_rn(0.5f * g_dis[s] * g_dis[d]));
    } else if (i < EE + NN) {
        int n = i - EE;
        atomicAdd(&g_Hah[(size_t)n * NN + n], __float2half_rn(0.5f * g_dis[n] * g_dis[n]));
    }
}

// ---------------- accumulate helper ----------------
#define ACC8(u, v)                                                              \
    {                                                                           \
        __half2* hp_ = (__half2*)&(u);                                          \
        float2 f0_ = __half22float2(hp_[0]);                                    \
        float2 f1_ = __half22float2(hp_[1]);                                    \
        float2 f2_ = __half22float2(hp_[2]);                                    \
        float2 f3_ = __half22float2(hp_[3]);                                    \
        acc[0] = fmaf((v), f0_.x, acc[0]); acc[1] = fmaf((v), f0_.y, acc[1]);   \
        acc[2] = fmaf((v), f1_.x, acc[2]); acc[3] = fmaf((v), f1_.y, acc[3]);   \
        acc[4] = fmaf((v), f2_.x, acc[4]); acc[5] = fmaf((v), f2_.y, acc[5]);   \
        acc[6] = fmaf((v), f3_.x, acc[6]); acc[7] = fmaf((v), f3_.y, acc[7]);   \
    }

// ---------------- P-build hop: O = 0.5 * Ahat * H + 0.5 * I ----------------
template <int DIR>
__global__ __launch_bounds__(256) void phop_kernel() {
    const __half* __restrict__ H = DIR ? g_Hbh : g_Hah;
    __half* __restrict__ O = DIR ? g_Hah : g_Hbh;
    int r = blockIdx.x;
    int c = (blockIdx.y << 11) + (threadIdx.x << 3);
    int beg = __ldg(&g_rowptr[r]);
    int end = __ldg(&g_rowptr[r + 1]);

    float acc[8];
#pragma unroll
    for (int i = 0; i < 8; i++) acc[i] = 0.f;

    int e = beg;
    for (; e + 4 <= end; e += 4) {
        int   i0 = __ldg(&g_cols[e + 0]);
        int   i1 = __ldg(&g_cols[e + 1]);
        int   i2 = __ldg(&g_cols[e + 2]);
        int   i3 = __ldg(&g_cols[e + 3]);
        float v0 = __ldg(&g_vals[e + 0]);
        float v1 = __ldg(&g_vals[e + 1]);
        float v2 = __ldg(&g_vals[e + 2]);
        float v3 = __ldg(&g_vals[e + 3]);
        uint4 u0 = __ldg((const uint4*)(H + ((size_t)i0 << 12) + c));
        uint4 u1 = __ldg((const uint4*)(H + ((size_t)i1 << 12) + c));
        uint4 u2 = __ldg((const uint4*)(H + ((size_t)i2 << 12) + c));
        uint4 u3 = __ldg((const uint4*)(H + ((size_t)i3 << 12) + c));
        ACC8(u0, v0);
        ACC8(u1, v1);
        ACC8(u2, v2);
        ACC8(u3, v3);
    }
    for (; e < end; e++) {
        int   i0 = __ldg(&g_cols[e]);
        float v0 = __ldg(&g_vals[e]);
        uint4 u0 = __ldg((const uint4*)(H + ((size_t)i0 << 12) + c));
        ACC8(u0, v0);
    }

    int dr = r - c;
    __half2 o[4];
#pragma unroll
    for (int q = 0; q < 4; q++) {
        float f0 = 0.5f * acc[2 * q];
        float f1 = 0.5f * acc[2 * q + 1];
        if (dr == 2 * q) f0 += 0.5f;
        if (dr == 2 * q + 1) f1 += 0.5f;
        o[q] = __floats2half2_rn(f0, f1);
    }
    *(uint4*)(O + ((size_t)r << 12) + c) = *(uint4*)o;
}

// ---------------- thin hop on Y (1024 cols) ----------------
// S == 0: Y0 -> Ya ; S == 1: Ya -> Yb ; S == 2: Yb -> Ya
template <int S>
__global__ __launch_bounds__(128) void thop_kernel() {
    const __half* __restrict__ H = (S == 0) ? g_Y0 : ((S == 1) ? g_Ya : g_Yb);
    __half* __restrict__ O = (S == 0) ? g_Ya : ((S == 1) ? g_Yb : g_Ya);
    int r = blockIdx.x;
    int c = threadIdx.x << 3;
    int beg = __ldg(&g_rowptr[r]);
    int end = __ldg(&g_rowptr[r + 1]);

    float acc[8];
#pragma unroll
    for (int i = 0; i < 8; i++) acc[i] = 0.f;

    int e = beg;
    for (; e + 4 <= end; e += 4) {
        int   i0 = __ldg(&g_cols[e + 0]);
        int   i1 = __ldg(&g_cols[e + 1]);
        int   i2 = __ldg(&g_cols[e + 2]);
        int   i3 = __ldg(&g_cols[e + 3]);
        float v0 = __ldg(&g_vals[e + 0]);
        float v1 = __ldg(&g_vals[e + 1]);
        float v2 = __ldg(&g_vals[e + 2]);
        float v3 = __ldg(&g_vals[e + 3]);
        uint4 u0 = __ldg((const uint4*)(H + ((size_t)i0 << 10) + c));
        uint4 u1 = __ldg((const uint4*)(H + ((size_t)i1 << 10) + c));
        uint4 u2 = __ldg((const uint4*)(H + ((size_t)i2 << 10) + c));
        uint4 u3 = __ldg((const uint4*)(H + ((size_t)i3 << 10) + c));
        ACC8(u0, v0);
        ACC8(u1, v1);
        ACC8(u2, v2);
        ACC8(u3, v3);
    }
    for (; e < end; e++) {
        int   i0 = __ldg(&g_cols[e]);
        float v0 = __ldg(&g_vals[e]);
        uint4 u0 = __ldg((const uint4*)(H + ((size_t)i0 << 10) + c));
        ACC8(u0, v0);
    }

    uint4 ux = __ldg((const uint4*)(g_Y0 + ((size_t)r << 10) + c));
    __half2* xp = (__half2*)&ux;
    __half2 o[4];
#pragma unroll
    for (int q = 0; q < 4; q++) {
        float2 xf = __half22float2(xp[q]);
        o[q] = __floats2half2_rn(0.5f * acc[2 * q] + 0.5f * xf.x,
                                 0.5f * acc[2 * q + 1] + 0.5f * xf.y);
    }
    *(uint4*)(O + ((size_t)r << 10) + c) = *(uint4*)o;
}

// ---------------- prescale: Ya[:, 0:512] = -2 * Yb[:, 0:512] ----------------
__global__ void prescale_kernel() {
    int r = blockIdx.x;
    int c = threadIdx.x << 3;
    uint4 u = *(const uint4*)(g_Yb + ((size_t)r << 10) + c);
    __half2* hp = (__half2*)&u;
    __half2 m2 = __floats2half2_rn(-2.f, -2.f);
#pragma unroll
    for (int q = 0; q < 4; q++) hp[q] = __hmul2(hp[q], m2);
    *(uint4*)(g_Ya + ((size_t)r << 10) + c) = u;
}

// ---------------- a = P*u, b = P*1 ----------------
__global__ __launch_bounds__(256) void matvec_kernel() {
    int lane = threadIdx.x & 31;
    int wid = threadIdx.x >> 5;
    int r = blockIdx.x * 8 + wid;
    const __half* Pr = g_Hbh + ((size_t)r << 12);
    float sa = 0.f, sb = 0.f;
    for (int t = lane; t < NN / 8; t += 32) {
        uint4 u = __ldg((const uint4*)(Pr + t * 8));
        __half2* hp = (__half2*)&u;
        float4 w0 = __ldg((const float4*)(g_sq + t * 8));
        float4 w1 = __ldg((const float4*)(g_sq + t * 8 + 4));
        float2 f0 = __half22float2(hp[0]);
        float2 f1 = __half22float2(hp[1]);
        float2 f2 = __half22float2(hp[2]);
        float2 f3 = __half22float2(hp[3]);
        sa += f0.x * w0.x + f0.y * w0.y + f1.x * w0.z + f1.y * w0.w
            + f2.x * w1.x + f2.y * w1.y + f3.x * w1.z + f3.y * w1.w;
        sb += f0.x + f0.y + f1.x + f1.y + f2.x + f2.y + f3.x + f3.y;
    }
#pragma unroll
    for (int o = 16; o > 0; o >>= 1) {
        sa += __shfl_xor_sync(0xffffffffu, sa, o);
        sb += __shfl_xor_sync(0xffffffffu, sb, o);
    }
    if (lane == 0) { g_a[r] = sa; g_b[r] = sb; }
}

// ---------------- fused final GEMM (wmma, fp16->fp32) ----------------
// out = P*P^T - 2*(pXw)(pX)^T + a*b^T + b*a^T, diag /(deg_row+1).
// 4 warps, 64x64 warp tiles (2x2 grid): 0.5 fragment-loads per MMA (was 0.75).
#define GKT 32
#define GP 40     // smem pitch (halves)
#define EPLD 136  // epilogue float pitch (mult of 4)

__global__ __launch_bounds__(128) void final_gemm_kernel(float* __restrict__ out) {
    __shared__ alignas(16) unsigned char sraw[2 * 128 * GP * 2 * 2]; // 40960 B
    __half* As = (__half*)sraw;                    // [2][128][GP]
    __half* Bs = (__half*)(sraw + 2 * 128 * GP * 2);
    float* ep = (float*)sraw;                      // epilogue reuse (34816 B)

    int tid = threadIdx.x;
    int wid = tid >> 5;          // 0..3
    int warp_m = wid >> 1;       // 0..1  (64-row slab)
    int warp_n = wid & 1;        // 0..1  (64-col slab)

    int bid = blockIdx.x;
    int bi = (int)((sqrtf(8.f * (float)bid + 1.f) - 1.f) * 0.5f);
    while ((bi + 1) * (bi + 2) / 2 <= bid) bi++;
    while (bi * (bi + 1) / 2 > bid) bi--;
    int bj = bid - bi * (bi + 1) / 2;
    int i0 = bi << 7;
    int j0 = bj << 7;

    wmma::fragment<wmma::accumulator, 16, 16, 16, float> c[4][4];
#pragma unroll
    for (int mi = 0; mi < 4; mi++)
#pragma unroll
        for (int ni = 0; ni < 4; ni++) wmma::fill_fragment(c[mi][ni], 0.f);

    auto stage = [&](int buf, const __half* bA, const __half* bB, int ldx, int k0) {
#pragma unroll
        for (int j = 0; j < 4; j++) {
            int idx = tid * 4 + j;       // 0..511
            int row = idx >> 2;          // 0..127
            int kq = idx & 3;            // granule of 8 halves
            const __half* ga = bA + (size_t)row * ldx + k0 + kq * 8;
            const __half* gb = bB + (size_t)row * ldx + k0 + kq * 8;
            unsigned int sa = (unsigned int)__cvta_generic_to_shared(As + buf * 128 * GP + row * GP + kq * 8);
            unsigned int sb = (unsigned int)__cvta_generic_to_shared(Bs + buf * 128 * GP + row * GP + kq * 8);
            asm volatile("cp.async.ca.shared.global [%0], [%1], 16;\n" ::"r"(sa), "l"(ga) : "memory");
            asm volatile("cp.async.ca.shared.global [%0], [%1], 16;\n" ::"r"(sb), "l"(gb) : "memory");
        }
        asm volatile("cp.async.commit_group;\n" ::: "memory");
    };

    auto compute = [&](int buf) {
#pragma unroll
        for (int kk = 0; kk < GKT; kk += 16) {
            wmma::fragment<wmma::matrix_a, 16, 16, 16, __half, wmma::row_major> af[4];
            wmma::fragment<wmma::matrix_b, 16, 16, 16, __half, wmma::col_major> bf[4];
#pragma unroll
            for (int mi = 0; mi < 4; mi++)
                wmma::load_matrix_sync(af[mi], As + buf * 128 * GP + (warp_m * 64 + mi * 16) * GP + kk, GP);
#pragma unroll
            for (int ni = 0; ni < 4; ni++)
                wmma::load_matrix_sync(bf[ni], Bs + buf * 128 * GP + (warp_n * 64 + ni * 16) * GP + kk, GP);
#pragma unroll
            for (int mi = 0; mi < 4; mi++)
#pragma unroll
                for (int ni = 0; ni < 4; ni++)
                    wmma::mma_sync(c[mi][ni], af[mi], bf[ni], c[mi][ni]);
        }
    };

    // segment 0: P * P^T (K = 4096)
    {
        const __half* bA = g_Hbh + ((size_t)i0 << 12);
        const __half* bB = g_Hbh + ((size_t)j0 << 12);
        stage(0, bA, bB, NN, 0);
        const int kn = NN / GKT; // 128
        for (int t = 0; t < kn; t++) {
            asm volatile("cp.async.wait_group 0;\n" ::: "memory");
            __syncthreads();
            if (t + 1 < kn) stage((t + 1) & 1, bA, bB, NN, (t + 1) * GKT);
            compute(t & 1);
        }
        __syncthreads();
    }
    // segment 1: (pXw) * (-2 pX)^T (K = 512)
    {
        const __half* bA = g_Yb + ((size_t)i0 << 10) + 512; // pXw
        const __half* bB = g_Ya + ((size_t)j0 << 10);       // -2*pX
        stage(0, bA, bB, 1024, 0);
        const int kn = 512 / GKT; // 16
        for (int t = 0; t < kn; t++) {
            asm volatile("cp.async.wait_group 0;\n" ::: "memory");
            __syncthreads();
            if (t + 1 < kn) stage((t + 1) & 1, bA, bB, 1024, (t + 1) * GKT);
            compute(t & 1);
        }
    }

    // epilogue: two 64-row phases through smem
    for (int p = 0; p < 2; p++) {
        __syncthreads();
        if (warp_m == p) {
#pragma unroll
            for (int mi = 0; mi < 4; mi++)
#pragma unroll
                for (int ni = 0; ni < 4; ni++)
                    wmma::store_matrix_sync(ep + (mi * 16) * EPLD + warp_n * 64 + ni * 16,
                                            c[mi][ni], EPLD, wmma::mem_row_major);
        }
        __syncthreads();

        int row0 = i0 + p * 64;

        // primary: 64 rows x 128 cols over 128 threads
        {
            int lj = (tid & 15) << 3;
#pragma unroll
            for (int q = 0; q < 8; q++) {
                int li = (tid >> 4) + q * 8;
                int gi = row0 + li;
                float ai = __ldg(&g_a[gi]);
                float bi_ = __ldg(&g_b[gi]);
                float tmp[8];
#pragma unroll
                for (int jj = 0; jj < 8; jj++) {
                    int gj = j0 + lj + jj;
                    float v = ep[li * EPLD + lj + jj] + ai * __ldg(&g_b[gj]) + bi_ * __ldg(&g_a[gj]);
                    if (gi == gj) v *= 1.f / ((float)__ldg(&g_degrow[gi]) + 1.f);
                    tmp[jj] = v;
                }
                size_t off = ((size_t)gi << 12) + j0 + lj;
                *(float4*)(out + off) = *(float4*)tmp;
                *(float4*)(out + off + 4) = *(float4*)(tmp + 4);
            }
        }

        // mirror (transposed) for off-diagonal blocks: 128 gj rows x 64 cols
        if (bi != bj) {
            int im = (tid & 7) << 3;
#pragma unroll
            for (int q = 0; q < 8; q++) {
                int jm = (tid >> 3) + q * 16;
                int gj = j0 + jm;
                float aj = __ldg(&g_a[gj]);
                float bj_ = __ldg(&g_b[gj]);
                float tmp[8];
#pragma unroll
                for (int ii = 0; ii < 8; ii++) {
                    int gi = row0 + im + ii;
                    tmp[ii] = ep[(im + ii) * EPLD + jm] + __ldg(&g_a[gi]) * bj_ + __ldg(&g_b[gi]) * aj;
                }
                size_t off = ((size_t)gj << 12) + row0 + im;
                *(float4*)(out + off) = *(float4*)tmp;
                *(float4*)(out + off + 4) = *(float4*)(tmp + 4);
            }
        }
    }
}

extern "C" void kernel_launch(void* const* d_in, const int* in_sizes, int n_in,
                              void* d_out, int out_size) {
    const float* x = (const float*)d_in[0];
    const float* w = (const float*)d_in[1];
    const int* ei = (const int*)d_in[2];
    const int* src = ei;
    const int* dst = ei + EE;
    float* out = (float*)d_out;

    // ---- fork: side stream starts sq (depends only on inputs) ----
    cudaEventRecord(hx.eRoot, 0);
    cudaStreamWaitEvent(hx.side, hx.eRoot, 0);
    sq_kernel<<<NN, 128, 0, hx.side>>>(x, w);
    cudaEventRecord(hx.eSq, hx.side);

    // ---- main: CSR build ----
    init_kernel<<<(NN + 255) / 256, 256>>>();
    count_kernel<<<(EE + 255) / 256, 256>>>(src, dst);
    scan_kernel<<<1, 1024>>>();
    fill_kernel<<<(EE + NN + 255) / 256, 256>>>(src, dst);
    cudaEventRecord(hx.eCsr, 0);

    // ---- side: thin hops (need CSR + sq) + separate prescale ----
    cudaStreamWaitEvent(hx.side, hx.eCsr, 0);
    thop_kernel<0><<<NN, 128, 0, hx.side>>>();   // Y0 -> Ya
    thop_kernel<1><<<NN, 128, 0, hx.side>>>();   // Ya -> Yb
    for (int h = 3; h <= 10; h++) {
        if (h & 1) thop_kernel<2><<<NN, 128, 0, hx.side>>>(); // Yb -> Ya
        else       thop_kernel<1><<<NN, 128, 0, hx.side>>>(); // Ya -> Yb
    }
    // result [pX | pXw] in g_Yb; prescale reads Yb, writes Ya (no race)
    prescale_kernel<<<NN, 64, 0, hx.side>>>();
    cudaEventRecord(hx.eSide, hx.side);

    // ---- main: P chain (wait for sq: matvec reads g_sq) ----
    cudaStreamWaitEvent(0, hx.eSq, 0);
    p1_init_kernel<<<dim3(NN, 2), 256>>>();
    p1_scatter_kernel<<<(EE + NN + 255) / 256, 256>>>(src, dst);
    dim3 gp(NN, 2);
    for (int h = 0; h < 9; h++) {
        if (h & 1) phop_kernel<1><<<gp, 256>>>();
        else       phop_kernel<0><<<gp, 256>>>();
    }
    matvec_kernel<<<NN / 8, 256>>>();   // needs g_Hbh (P) + g_sq

    // ---- join, then final GEMM ----
    cudaStreamWaitEvent(0, hx.eSide, 0);
    final_gemm_kernel<<<528, 128>>>(out);
    (void)in_sizes; (void)n_in; (void)out_size;
}

// round 17
// speedup vs baseline: 1.0064x; 1.0064x over previous
#include <cuda_runtime.h>
#include <cuda_fp16.h>
#include <mma.h>

using namespace nvcuda;

#define NN 4096
#define DD 512
#define EE 65536

// ---------------- static device scratch (allocation-free rule) ----------------
__device__ __half g_Hah[(size_t)NN * NN];     // P ping
__device__ __half g_Hbh[(size_t)NN * NN];     // P pong (final P lands here)
__device__ __half g_Y0[(size_t)NN * 1024];    // [X | Xw] fp16
__device__ __half g_Ya[(size_t)NN * 1024];    // thin ping / final -2*pX
__device__ __half g_Yb[(size_t)NN * 1024];    // thin pong (final [pX | pXw])
__device__ float g_a[NN];                     // P*u
__device__ float g_b[NN];                     // P*1
__device__ int   g_rowptr[NN + 1];
__device__ int   g_cur[NN];
__device__ int   g_cols[EE + NN];
__device__ float g_vals[EE + NN];
__device__ float g_dis[NN];
__device__ float g_sq[NN];
__device__ int   g_degdst[NN];
__device__ int   g_degrow[NN];

// ---------------- streams/events for fork-join overlap (created at load time,
// host-side only; no device allocation inside kernel_launch) ----------------
struct HxStreams {
    cudaStream_t side;
    cudaEvent_t eRoot, eCsr, eSq, eSide;
    HxStreams() {
        cudaStreamCreateWithFlags(&side, cudaStreamNonBlocking);
        cudaEventCreateWithFlags(&eRoot, cudaEventDisableTiming);
        cudaEventCreateWithFlags(&eCsr, cudaEventDisableTiming);
        cudaEventCreateWithFlags(&eSq, cudaEventDisableTiming);
        cudaEventCreateWithFlags(&eSide, cudaEventDisableTiming);
    }
};
static HxStreams hx;

// ---------------- graph preprocessing ----------------
__global__ void init_kernel() {
    int i = blockIdx.x * blockDim.x + threadIdx.x;
    if (i < NN) { g_degdst[i] = 1; g_degrow[i] = 0; }
}

__global__ void count_kernel(const int* __restrict__ src, const int* __restrict__ dst) {
    int i = blockIdx.x * blockDim.x + threadIdx.x;
    if (i < EE) {
        atomicAdd(&g_degdst[dst[i]], 1);
        atomicAdd(&g_degrow[src[i]], 1);
    }
}

// single block, 1024 threads, 4 elements each: exclusive scan of g_degdst -> rowptr
__global__ void scan_kernel() {
    __shared__ int part[1024];
    int t = threadIdx.x;
    int v[4];
    int s = 0;
#pragma unroll
    for (int j = 0; j < 4; j++) { v[j] = g_degdst[t * 4 + j]; s += v[j]; }
    part[t] = s;
    __syncthreads();
    for (int off = 1; off < 1024; off <<= 1) {
        int x = 0;
        if (t >= off) x = part[t - off];
        __syncthreads();
        if (t >= off) part[t] += x;
        __syncthreads();
    }
    int base = part[t] - s;
    int run = base;
#pragma unroll
    for (int j = 0; j < 4; j++) {
        int idx = t * 4 + j;
        g_rowptr[idx] = run;
        g_cur[idx] = run;
        g_dis[idx] = rsqrtf((float)v[j]);
        run += v[j];
    }
    if (t == 1023) g_rowptr[NN] = part[1023];
}

__global__ void fill_kernel(const int* __restrict__ src, const int* __restrict__ dst) {
    int i = blockIdx.x * blockDim.x + threadIdx.x;
    if (i < EE) {
        int s = src[i], d = dst[i];
        int p = atomicAdd(&g_cur[d], 1);
        g_cols[p] = s;
        g_vals[p] = g_dis[s] * g_dis[d];
    } else if (i < EE + NN) {
        int n = i - EE;
        int p = atomicAdd(&g_cur[n], 1);
        g_cols[p] = n;
        g_vals[p] = g_dis[n] * g_dis[n];
    }
}

// ---------------- sq + Y0 build (side stream; inputs only) ----------------
__global__ void sq_kernel(const float* __restrict__ x, const float* __restrict__ w) {
    __shared__ float red[4];
    int r = blockIdx.x;
    int t = threadIdx.x;
    float s = 0.f;
    for (int d = t; d < DD; d += 128) {
        float xv = x[r * DD + d];
        float wv = w[d];
        s += wv * xv * xv;
        g_Y0[(size_t)r * 1024 + d] = __float2half_rn(xv);
        g_Y0[(size_t)r * 1024 + 512 + d] = __float2half_rn(xv * wv);
    }
#pragma unroll
    for (int o = 16; o > 0; o >>= 1) s += __shfl_xor_sync(0xffffffffu, s, o);
    if ((t & 31) == 0) red[t >> 5] = s;
    __syncthreads();
    if (t == 0) g_sq[r] = red[0] + red[1] + red[2] + red[3];
}

// ---------------- P1 = 0.5*Ahat + 0.5*I ----------------
__global__ void p1_init_kernel() {
    int r = blockIdx.x;
    int c = (blockIdx.y << 11) + (threadIdx.x << 3);
    uint4 z = make_uint4(0u, 0u, 0u, 0u);
    *(uint4*)(g_Hah + (size_t)r * NN + c) = z;
    if (r >= c && r < c + 8) g_Hah[(size_t)r * NN + r] = __float2half_rn(0.5f);
}

__global__ void p1_scatter_kernel(const int* __restrict__ src, const int* __restrict__ dst) {
    int i = blockIdx.x * blockDim.x + threadIdx.x;
    if (i < EE) {
        int s = src[i], d = dst[i];
        atomicAdd(&g_Hah[(size_t)d * NN + s], __float2half_rn(0.5f * g_dis[s] * g_dis[d]));
    } else if (i < EE + NN) {
        int n = i - EE;
        atomicAdd(&g_Hah[(size_t)n * NN + n], __float2half_rn(0.5f * g_dis[n] * g_dis[n]));
    }
}

// ---------------- accumulate helper ----------------
#define ACC8(u, v)                                                              \
    {                                                                           \
        __half2* hp_ = (__half2*)&(u);                                          \
        float2 f0_ = __half22float2(hp_[0]);                                    \
        float2 f1_ = __half22float2(hp_[1]);                                    \
        float2 f2_ = __half22float2(hp_[2]);                                    \
        float2 f3_ = __half22float2(hp_[3]);                                    \
        acc[0] = fmaf((v), f0_.x, acc[0]); acc[1] = fmaf((v), f0_.y, acc[1]);   \
        acc[2] = fmaf((v), f1_.x, acc[2]); acc[3] = fmaf((v), f1_.y, acc[3]);   \
        acc[4] = fmaf((v), f2_.x, acc[4]); acc[5] = fmaf((v), f2_.y, acc[5]);   \
        acc[6] = fmaf((v), f3_.x, acc[6]); acc[7] = fmaf((v), f3_.y, acc[7]);   \
    }

// ---------------- P-build hop: O = 0.5 * Ahat * H + 0.5 * I ----------------
template <int DIR>
__global__ __launch_bounds__(256) void phop_kernel() {
    const __half* __restrict__ H = DIR ? g_Hbh : g_Hah;
    __half* __restrict__ O = DIR ? g_Hah : g_Hbh;
    int r = blockIdx.x;
    int c = (blockIdx.y << 11) + (threadIdx.x << 3);
    int beg = __ldg(&g_rowptr[r]);
    int end = __ldg(&g_rowptr[r + 1]);

    float acc[8];
#pragma unroll
    for (int i = 0; i < 8; i++) acc[i] = 0.f;

    int e = beg;
    for (; e + 4 <= end; e += 4) {
        int   i0 = __ldg(&g_cols[e + 0]);
        int   i1 = __ldg(&g_cols[e + 1]);
        int   i2 = __ldg(&g_cols[e + 2]);
        int   i3 = __ldg(&g_cols[e + 3]);
        float v0 = __ldg(&g_vals[e + 0]);
        float v1 = __ldg(&g_vals[e + 1]);
        float v2 = __ldg(&g_vals[e + 2]);
        float v3 = __ldg(&g_vals[e + 3]);
        uint4 u0 = __ldg((const uint4*)(H + ((size_t)i0 << 12) + c));
        uint4 u1 = __ldg((const uint4*)(H + ((size_t)i1 << 12) + c));
        uint4 u2 = __ldg((const uint4*)(H + ((size_t)i2 << 12) + c));
        uint4 u3 = __ldg((const uint4*)(H + ((size_t)i3 << 12) + c));
        ACC8(u0, v0);
        ACC8(u1, v1);
        ACC8(u2, v2);
        ACC8(u3, v3);
    }
    for (; e < end; e++) {
        int   i0 = __ldg(&g_cols[e]);
        float v0 = __ldg(&g_vals[e]);
        uint4 u0 = __ldg((const uint4*)(H + ((size_t)i0 << 12) + c));
        ACC8(u0, v0);
    }

    int dr = r - c;
    __half2 o[4];
#pragma unroll
    for (int q = 0; q < 4; q++) {
        float f0 = 0.5f * acc[2 * q];
        float f1 = 0.5f * acc[2 * q + 1];
        if (dr == 2 * q) f0 += 0.5f;
        if (dr == 2 * q + 1) f1 += 0.5f;
        o[q] = __floats2half2_rn(f0, f1);
    }
    *(uint4*)(O + ((size_t)r << 12) + c) = *(uint4*)o;
}

// ---------------- thin hop on Y (1024 cols) ----------------
// S == 0: Y0 -> Ya ; S == 1: Ya -> Yb ; S == 2: Yb -> Ya
template <int S>
__global__ __launch_bounds__(128) void thop_kernel() {
    const __half* __restrict__ H = (S == 0) ? g_Y0 : ((S == 1) ? g_Ya : g_Yb);
    __half* __restrict__ O = (S == 0) ? g_Ya : ((S == 1) ? g_Yb : g_Ya);
    int r = blockIdx.x;
    int c = threadIdx.x << 3;
    int beg = __ldg(&g_rowptr[r]);
    int end = __ldg(&g_rowptr[r + 1]);

    float acc[8];
#pragma unroll
    for (int i = 0; i < 8; i++) acc[i] = 0.f;

    int e = beg;
    for (; e + 4 <= end; e += 4) {
        int   i0 = __ldg(&g_cols[e + 0]);
        int   i1 = __ldg(&g_cols[e + 1]);
        int   i2 = __ldg(&g_cols[e + 2]);
        int   i3 = __ldg(&g_cols[e + 3]);
        float v0 = __ldg(&g_vals[e + 0]);
        float v1 = __ldg(&g_vals[e + 1]);
        float v2 = __ldg(&g_vals[e + 2]);
        float v3 = __ldg(&g_vals[e + 3]);
        uint4 u0 = __ldg((const uint4*)(H + ((size_t)i0 << 10) + c));
        uint4 u1 = __ldg((const uint4*)(H + ((size_t)i1 << 10) + c));
        uint4 u2 = __ldg((const uint4*)(H + ((size_t)i2 << 10) + c));
        uint4 u3 = __ldg((const uint4*)(H + ((size_t)i3 << 10) + c));
        ACC8(u0, v0);
        ACC8(u1, v1);
        ACC8(u2, v2);
        ACC8(u3, v3);
    }
    for (; e < end; e++) {
        int   i0 = __ldg(&g_cols[e]);
        float v0 = __ldg(&g_vals[e]);
        uint4 u0 = __ldg((const uint4*)(H + ((size_t)i0 << 10) + c));
        ACC8(u0, v0);
    }

    uint4 ux = __ldg((const uint4*)(g_Y0 + ((size_t)r << 10) + c));
    __half2* xp = (__half2*)&ux;
    __half2 o[4];
#pragma unroll
    for (int q = 0; q < 4; q++) {
        float2 xf = __half22float2(xp[q]);
        o[q] = __floats2half2_rn(0.5f * acc[2 * q] + 0.5f * xf.x,
                                 0.5f * acc[2 * q + 1] + 0.5f * xf.y);
    }
    *(uint4*)(O + ((size_t)r << 10) + c) = *(uint4*)o;
}

// ---------------- prescale: Ya[:, 0:512] = -2 * Yb[:, 0:512] ----------------
__global__ void prescale_kernel() {
    int r = blockIdx.x;
    int c = threadIdx.x << 3;
    uint4 u = *(const uint4*)(g_Yb + ((size_t)r << 10) + c);
    __half2* hp = (__half2*)&u;
    __half2 m2 = __floats2half2_rn(-2.f, -2.f);
#pragma unroll
    for (int q = 0; q < 4; q++) hp[q] = __hmul2(hp[q], m2);
    *(uint4*)(g_Ya + ((size_t)r << 10) + c) = u;
}

// ---------------- a = P*u, b = P*1 ----------------
__global__ __launch_bounds__(256) void matvec_kernel() {
    int lane = threadIdx.x & 31;
    int wid = threadIdx.x >> 5;
    int r = blockIdx.x * 8 + wid;
    const __half* Pr = g_Hbh + ((size_t)r << 12);
    float sa = 0.f, sb = 0.f;
    for (int t = lane; t < NN / 8; t += 32) {
        uint4 u = __ldg((const uint4*)(Pr + t * 8));
        __half2* hp = (__half2*)&u;
        float4 w0 = __ldg((const float4*)(g_sq + t * 8));
        float4 w1 = __ldg((const float4*)(g_sq + t * 8 + 4));
        float2 f0 = __half22float2(hp[0]);
        float2 f1 = __half22float2(hp[1]);
        float2 f2 = __half22float2(hp[2]);
        float2 f3 = __half22float2(hp[3]);
        sa += f0.x * w0.x + f0.y * w0.y + f1.x * w0.z + f1.y * w0.w
            + f2.x * w1.x + f2.y * w1.y + f3.x * w1.z + f3.y * w1.w;
        sb += f0.x + f0.y + f1.x + f1.y + f2.x + f2.y + f3.x + f3.y;
    }
#pragma unroll
    for (int o = 16; o > 0; o >>= 1) {
        sa += __shfl_xor_sync(0xffffffffu, sa, o);
        sb += __shfl_xor_sync(0xffffffffu, sb, o);
    }
    if (lane == 0) { g_a[r] = sa; g_b[r] = sb; }
}

// ---------------- fused final GEMM (wmma, fp16->fp32) ----------------
// out = P*P^T - 2*(pXw)(pX)^T + a*b^T + b*a^T, diag /(deg_row+1).
// 256x128 CTA tile, 8 warps x (64x64) warp tiles: 0.5 LDSM/MMA AND 2 warps/SMSP.
// Triangular tiles (bi2, bj) with bj <= 2*bi2+1 -> 272 CTAs.
#define GKT 32
#define GP 40     // smem pitch (halves)
#define EPLD 136  // epilogue float pitch (mult of 4)
// dynamic smem: A[2][256][GP] + B[2][128][GP] halves = 61440 B
#define GEMM_SMEM (2 * 256 * GP * 2 + 2 * 128 * GP * 2)

__global__ __launch_bounds__(256, 1) void final_gemm_kernel(float* __restrict__ out) {
    extern __shared__ unsigned char dyn[];
    __half* As = (__half*)dyn;                          // [2][256][GP]
    __half* Bs = (__half*)(dyn + 2 * 256 * GP * 2);     // [2][128][GP]
    float* ep = (float*)dyn;                            // epilogue reuse (34816 B)

    int tid = threadIdx.x;
    int wid = tid >> 5;          // 0..7
    int warp_m = wid >> 1;       // 0..3  (64-row slab of 256)
    int warp_n = wid & 1;        // 0..1  (64-col slab of 128)

    // decode tile: bid -> (bi2, bj), bj in [0, 2*bi2+2); cum(bi2) = bi2^2+bi2
    int bid = blockIdx.x;
    int bi2 = (int)((sqrtf(4.f * (float)bid + 1.f) - 1.f) * 0.5f);
    while ((bi2 + 1) * (bi2 + 1) + (bi2 + 1) <= bid) bi2++;
    while (bi2 * bi2 + bi2 > bid) bi2--;
    int bj = bid - (bi2 * bi2 + bi2);
    int i0 = bi2 << 8;   // 256-row slab
    int j0 = bj << 7;    // 128-col slab

    wmma::fragment<wmma::accumulator, 16, 16, 16, float> c[4][4];
#pragma unroll
    for (int mi = 0; mi < 4; mi++)
#pragma unroll
        for (int ni = 0; ni < 4; ni++) wmma::fill_fragment(c[mi][ni], 0.f);

    auto stage = [&](int buf, const __half* bA, const __half* bB, int ldx, int k0) {
        // A: 256 rows x 4 granules = 1024 cp.asyncs -> 4/thread
#pragma unroll
        for (int j = 0; j < 4; j++) {
            int idx = tid * 4 + j;
            int row = idx >> 2;
            int kq = idx & 3;
            const __half* ga = bA + (size_t)row * ldx + k0 + kq * 8;
            unsigned int sa = (unsigned int)__cvta_generic_to_shared(As + buf * 256 * GP + row * GP + kq * 8);
            asm volatile("cp.async.ca.shared.global [%0], [%1], 16;\n" ::"r"(sa), "l"(ga) : "memory");
        }
        // B: 128 rows x 4 granules = 512 cp.asyncs -> 2/thread
#pragma unroll
        for (int j = 0; j < 2; j++) {
            int idx = tid * 2 + j;
            int row = idx >> 2;
            int kq = idx & 3;
            const __half* gb = bB + (size_t)row * ldx + k0 + kq * 8;
            unsigned int sb = (unsigned int)__cvta_generic_to_shared(Bs + buf * 128 * GP + row * GP + kq * 8);
            asm volatile("cp.async.ca.shared.global [%0], [%1], 16;\n" ::"r"(sb), "l"(gb) : "memory");
        }
        asm volatile("cp.async.commit_group;\n" ::: "memory");
    };

    auto compute = [&](int buf) {
#pragma unroll
        for (int kk = 0; kk < GKT; kk += 16) {
            wmma::fragment<wmma::matrix_a, 16, 16, 16, __half, wmma::row_major> af[4];
            wmma::fragment<wmma::matrix_b, 16, 16, 16, __half, wmma::col_major> bf[4];
#pragma unroll
            for (int mi = 0; mi < 4; mi++)
                wmma::load_matrix_sync(af[mi], As + buf * 256 * GP + (warp_m * 64 + mi * 16) * GP + kk, GP);
#pragma unroll
            for (int ni = 0; ni < 4; ni++)
                wmma::load_matrix_sync(bf[ni], Bs + buf * 128 * GP + (warp_n * 64 + ni * 16) * GP + kk, GP);
#pragma unroll
            for (int mi = 0; mi < 4; mi++)
#pragma unroll
                for (int ni = 0; ni < 4; ni++)
                    wmma::mma_sync(c[mi][ni], af[mi], bf[ni], c[mi][ni]);
        }
    };

    // segment 0: P * P^T (K = 4096)
    {
        const __half* bA = g_Hbh + ((size_t)i0 << 12);
        const __half* bB = g_Hbh + ((size_t)j0 << 12);
        stage(0, bA, bB, NN, 0);
        const int kn = NN / GKT; // 128
        for (int t = 0; t < kn; t++) {
            asm volatile("cp.async.wait_group 0;\n" ::: "memory");
            __syncthreads();
            if (t + 1 < kn) stage((t + 1) & 1, bA, bB, NN, (t + 1) * GKT);
            compute(t & 1);
        }
        __syncthreads();
    }
    // segment 1: (pXw) * (-2 pX)^T (K = 512)
    {
        const __half* bA = g_Yb + ((size_t)i0 << 10) + 512; // pXw
        const __half* bB = g_Ya + ((size_t)j0 << 10);       // -2*pX
        stage(0, bA, bB, 1024, 0);
        const int kn = 512 / GKT; // 16
        for (int t = 0; t < kn; t++) {
            asm volatile("cp.async.wait_group 0;\n" ::: "memory");
            __syncthreads();
            if (t + 1 < kn) stage((t + 1) & 1, bA, bB, 1024, (t + 1) * GKT);
            compute(t & 1);
        }
    }

    // epilogue: four 64-row phases; phase p covers global rows i0 + p*64
    for (int p = 0; p < 4; p++) {
        int gb = 2 * bi2 + (p >> 1);   // global 128-row block index of this 64-row slab's parent
        __syncthreads();
        if (warp_m == p) {
#pragma unroll
            for (int mi = 0; mi < 4; mi++)
#pragma unroll
                for (int ni = 0; ni < 4; ni++)
                    wmma::store_matrix_sync(ep + (mi * 16) * EPLD + warp_n * 64 + ni * 16,
                                            c[mi][ni], EPLD, wmma::mem_row_major);
        }
        __syncthreads();

        if (gb < bj) continue;  // upper-triangle slab: discard

        int row0 = i0 + p * 64;

        // primary: 64 rows x 128 cols over 256 threads
        {
            int lj = (tid & 15) << 3;
#pragma unroll
            for (int q = 0; q < 4; q++) {
                int li = (tid >> 4) + q * 16;
                int gi = row0 + li;
                float ai = __ldg(&g_a[gi]);
                float bi_ = __ldg(&g_b[gi]);
                float tmp[8];
#pragma unroll
                for (int jj = 0; jj < 8; jj++) {
                    int gj = j0 + lj + jj;
                    float v = ep[li * EPLD + lj + jj] + ai * __ldg(&g_b[gj]) + bi_ * __ldg(&g_a[gj]);
                    if (gi == gj) v *= 1.f / ((float)__ldg(&g_degrow[gi]) + 1.f);
                    tmp[jj] = v;
                }
                size_t off = ((size_t)gi << 12) + j0 + lj;
                *(float4*)(out + off) = *(float4*)tmp;
                *(float4*)(out + off + 4) = *(float4*)(tmp + 4);
            }
        }

        // mirror (transposed) only for strictly-below-diagonal slabs
        if (gb > bj) {
            int im = (tid & 7) << 3;
#pragma unroll
            for (int q = 0; q < 4; q++) {
                int jm = (tid >> 3) + q * 32;
                int gj = j0 + jm;
                float aj = __ldg(&g_a[gj]);
                float bj_ = __ldg(&g_b[gj]);
                float tmp[8];
#pragma unroll
                for (int ii = 0; ii < 8; ii++) {
                    int gi = row0 + im + ii;
                    tmp[ii] = ep[(im + ii) * EPLD + jm] + __ldg(&g_a[gi]) * bj_ + __ldg(&g_b[gi]) * aj;
                }
                size_t off = ((size_t)gj << 12) + row0 + im;
                *(float4*)(out + off) = *(float4*)tmp;
                *(float4*)(out + off + 4) = *(float4*)(tmp + 4);
            }
        }
    }
}

extern "C" void kernel_launch(void* const* d_in, const int* in_sizes, int n_in,
                              void* d_out, int out_size) {
    const float* x = (const float*)d_in[0];
    const float* w = (const float*)d_in[1];
    const int* ei = (const int*)d_in[2];
    const int* src = ei;
    const int* dst = ei + EE;
    float* out = (float*)d_out;

    static bool attr_done = false;
    if (!attr_done) {
        cudaFuncSetAttribute(final_gemm_kernel,
                             cudaFuncAttributeMaxDynamicSharedMemorySize, GEMM_SMEM);
        attr_done = true;
    }

    // ---- fork: side stream starts sq (depends only on inputs) ----
    cudaEventRecord(hx.eRoot, 0);
    cudaStreamWaitEvent(hx.side, hx.eRoot, 0);
    sq_kernel<<<NN, 128, 0, hx.side>>>(x, w);
    cudaEventRecord(hx.eSq, hx.side);

    // ---- main: CSR build ----
    init_kernel<<<(NN + 255) / 256, 256>>>();
    count_kernel<<<(EE + 255) / 256, 256>>>(src, dst);
    scan_kernel<<<1, 1024>>>();
    fill_kernel<<<(EE + NN + 255) / 256, 256>>>(src, dst);
    cudaEventRecord(hx.eCsr, 0);

    // ---- side: thin hops (need CSR + sq) + separate prescale ----
    cudaStreamWaitEvent(hx.side, hx.eCsr, 0);
    thop_kernel<0><<<NN, 128, 0, hx.side>>>();   // Y0 -> Ya
    thop_kernel<1><<<NN, 128, 0, hx.side>>>();   // Ya -> Yb
    for (int h = 3; h <= 10; h++) {
        if (h & 1) thop_kernel<2><<<NN, 128, 0, hx.side>>>(); // Yb -> Ya
        else       thop_kernel<1><<<NN, 128, 0, hx.side>>>(); // Ya -> Yb
    }
    // result [pX | pXw] in g_Yb; prescale reads Yb, writes Ya (no race)
    prescale_kernel<<<NN, 64, 0, hx.side>>>();
    cudaEventRecord(hx.eSide, hx.side);

    // ---- main: P chain (wait for sq: matvec reads g_sq) ----
    cudaStreamWaitEvent(0, hx.eSq, 0);
    p1_init_kernel<<<dim3(NN, 2), 256>>>();
    p1_scatter_kernel<<<(EE + NN + 255) / 256, 256>>>(src, dst);
    dim3 gp(NN, 2);
    for (int h = 0; h < 9; h++) {
        if (h & 1) phop_kernel<1><<<gp, 256>>>();
        else       phop_kernel<0><<<gp, 256>>>();
    }
    matvec_kernel<<<NN / 8, 256>>>();   // needs g_Hbh (P) + g_sq

    // ---- join, then final GEMM ----
    cudaStreamWaitEvent(0, hx.eSide, 0);
    final_gemm_kernel<<<272, 256, GEMM_SMEM>>>(out);
    (void)in_sizes; (void)n_in; (void)out_size;
}